// round 8
// baseline (speedup 1.0000x reference)
#include <cuda_runtime.h>
#include <cstdint>

#define N_NODESC 100000
#define N_EDGESC 1000000
#define INV07 (1.0f/0.7f)
#define PAE_S1_OFF 128000000u   // flat offset of s=1 plane in [2,E,128]

// ---------------- scratch (static device globals; no allocation) ----------------
__device__ double g_sums[512];            // [0..255] sum (s*128+c), [256..511] sumsq
__device__ float  g_scale[256];
__device__ float  g_shift[256];
__device__ float  g_b2v[128];
__device__ int    g_sel;                  // 1 if cand1 is gamma, else 3
__device__ float  g_ew[N_EDGESC];
__device__ float  g_deg[N_NODESC];
__device__ float  g_dinv[N_NODESC];
__device__ float  g_xw[N_NODESC * 64];
__device__ float  g_agg[N_NODESC * 64];
__device__ float  g_h[N_NODESC * 64];

// ---------------- JAX threefry2x32 (exact core) ----------------
__host__ __device__ __forceinline__ void threefry2x32(
    uint32_t k0, uint32_t k1, uint32_t x0, uint32_t x1,
    uint32_t& o0, uint32_t& o1)
{
    uint32_t k2 = k0 ^ k1 ^ 0x1BD11BDAu;
    x0 += k0; x1 += k1;
#define TFR(r) { x0 += x1; x1 = (x1 << (r)) | (x1 >> (32 - (r))); x1 ^= x0; }
    TFR(13) TFR(15) TFR(26) TFR(6)   x0 += k1; x1 += k2 + 1u;
    TFR(17) TFR(29) TFR(16) TFR(24)  x0 += k2; x1 += k0 + 2u;
    TFR(13) TFR(15) TFR(26) TFR(6)   x0 += k0; x1 += k1 + 3u;
    TFR(17) TFR(29) TFR(16) TFR(24)  x0 += k1; x1 += k2 + 4u;
    TFR(13) TFR(15) TFR(26) TFR(6)   x0 += k2; x1 += k0 + 5u;
#undef TFR
    o0 = x0; o1 = x1;
}

// partitionable random_bits(32): bits(i) = o0 ^ o1 of threefry(key, hi(i)=0, lo(i)=i)
__device__ __forceinline__ uint32_t part_bits(uint32_t k0, uint32_t k1, uint32_t i)
{
    uint32_t a, b;
    threefry2x32(k0, k1, 0u, i, a, b);
    return a ^ b;
}

__device__ __forceinline__ float bits_to_uniform(uint32_t bits)
{
    return __uint_as_float((bits >> 9) | 0x3f800000u) - 1.0f;
}

// ---------------- init ----------------
__global__ void init_misc()
{
    int t = blockIdx.x * blockDim.x + threadIdx.x;
    if (t < 512) g_sums[t] = 0.0;
    if (t < N_NODESC) g_deg[t] = 1.0f;   // self-loop weight
}

// runtime disambiguation of gamma vs b2 among the two swappable 128-vectors
__global__ void select_gamma(const float* __restrict__ c1, const float* __restrict__ c3)
{
    float s1 = 0.f, s3 = 0.f;
    for (int i = 0; i < 128; i++) { s1 += fabsf(c1[i]); s3 += fabsf(c3[i]); }
    g_sel = (s1 >= s3) ? 1 : 3;
}

// ---------------- PAE BN statistics ----------------
__global__ void __launch_bounds__(128) pae_stats(
    const float* __restrict__ edgenet, const float* __restrict__ w1,
    const float* __restrict__ b1)
{
    int c = threadIdx.x;
    float w10 = w1[c], w11 = w1[128 + c], b1c = b1[c];
    int chunk = (N_EDGESC + gridDim.x - 1) / gridDim.x;
    int e0 = blockIdx.x * chunk;
    int e1 = min(N_EDGESC, e0 + chunk);
    float s0 = 0.f, q0 = 0.f, s1 = 0.f, q1 = 0.f;
    for (int e = e0; e < e1; e++) {
        float4 v = __ldg((const float4*)&edgenet[e * 4]);
        float h0 = fmaxf(fmaf(v.x, w10, fmaf(v.y, w11, b1c)), 0.f);
        float h1 = fmaxf(fmaf(v.z, w10, fmaf(v.w, w11, b1c)), 0.f);
        s0 += h0; q0 += h0 * h0;
        s1 += h1; q1 += h1 * h1;
    }
    atomicAdd(&g_sums[c],       (double)s0);
    atomicAdd(&g_sums[128 + c], (double)s1);
    atomicAdd(&g_sums[256 + c], (double)q0);
    atomicAdd(&g_sums[384 + c], (double)q1);
}

__global__ void pae_finalize(const float* __restrict__ c1, const float* __restrict__ c3,
                             const float* __restrict__ beta)
{
    int i = threadIdx.x;          // 0..255 (s*128+c)
    int c = i & 127;
    const float* gamma = (g_sel == 1) ? c1 : c3;
    const float* b2    = (g_sel == 1) ? c3 : c1;
    if (i < 128) g_b2v[i] = b2[i];
    double mean = g_sums[i] / (double)N_EDGESC;
    double var  = g_sums[256 + i] / (double)N_EDGESC - mean * mean;
    double sc   = (double)gamma[c] / sqrt(var + 1e-5);
    g_scale[i] = (float)sc;
    g_shift[i] = (float)((double)beta[c] - mean * sc);
}

// ---------------- PAE main: BN+dropout+Linear2+cosine per edge ----------------
// persistent blocks; each tile = 16 edges (32 rows of 128), GEMM vs w2 (128x128)
// w2 streamed from L2 (64 KB hot); smem only holds hT + tile edges (<48 KB)
__global__ void __launch_bounds__(128) pae_main(
    const float* __restrict__ edgenet, const float* __restrict__ w1,
    const float* __restrict__ b1, const float* __restrict__ w2,
    uint32_t kp0, uint32_t kp1)
{
    __shared__ float hT[128 * 36];      // [channel k][pair p], padded stride 36
    __shared__ float edg[64];           // 16 edges x 4
    __shared__ float b2s[128];

    int t = threadIdx.x;
    b2s[t] = g_b2v[t];

    int c = t;
    float w10 = w1[c], w11 = w1[128 + c], b1c = b1[c];
    float sc0 = g_scale[c], sh0 = g_shift[c];
    float sc1 = g_scale[128 + c], sh1 = g_shift[128 + c];

    int g  = t >> 4;            // 0..7 -> pair rows 4g..4g+3
    int c8 = (t & 15) * 8;
    int g4 = g * 4;

    const int numTiles = N_EDGESC / 16;
    for (int tile = blockIdx.x; tile < numTiles; tile += gridDim.x) {
        __syncthreads();        // protect hT/edg from previous iteration readers
        if (t < 16)
            *(float4*)&edg[t * 4] = __ldg(&((const float4*)edgenet)[tile * 16 + t]);
        __syncthreads();

        int e0 = tile * 16;
        // phase 1: h (BN + dropout); partitionable bits per element
        #pragma unroll 4
        for (int el = 0; el < 16; el++) {
            float xa0 = edg[el * 4 + 0], xb0 = edg[el * 4 + 1];
            float xa1 = edg[el * 4 + 2], xb1 = edg[el * 4 + 3];
            float hp0 = fmaxf(fmaf(xa0, w10, fmaf(xb0, w11, b1c)), 0.f);
            float hp1 = fmaxf(fmaf(xa1, w10, fmaf(xb1, w11, b1c)), 0.f);
            float hn0 = fmaf(hp0, sc0, sh0);
            float hn1 = fmaf(hp1, sc1, sh1);
            uint32_t i0 = (uint32_t)(e0 + el) * 128u + (uint32_t)c;
            float u0 = bits_to_uniform(part_bits(kp0, kp1, i0));
            float u1 = bits_to_uniform(part_bits(kp0, kp1, i0 + PAE_S1_OFF));
            hT[c * 36 + 2 * el]     = (u0 < 0.7f) ? hn0 * INV07 : 0.f;
            hT[c * 36 + 2 * el + 1] = (u1 < 0.7f) ? hn1 * INV07 : 0.f;
        }
        __syncthreads();

        // phase 2: y[32 rows][128] = h @ w2 ; register tile 4 rows x 8 cols
        float a0[8], a1[8], a2[8], a3[8];
        #pragma unroll
        for (int j = 0; j < 8; j++) { a0[j] = 0.f; a1[j] = 0.f; a2[j] = 0.f; a3[j] = 0.f; }

        #pragma unroll 4
        for (int k = 0; k < 128; k++) {
            float4 wA = __ldg((const float4*)&w2[k * 128 + c8]);
            float4 wB = __ldg((const float4*)&w2[k * 128 + c8 + 4]);
            float4 hv = *(const float4*)&hT[k * 36 + g4];
            float wv[8] = {wA.x, wA.y, wA.z, wA.w, wB.x, wB.y, wB.z, wB.w};
            #pragma unroll
            for (int j = 0; j < 8; j++) {
                a0[j] = fmaf(hv.x, wv[j], a0[j]);
                a1[j] = fmaf(hv.y, wv[j], a1[j]);
                a2[j] = fmaf(hv.z, wv[j], a2[j]);
                a3[j] = fmaf(hv.w, wv[j], a3[j]);
            }
        }

        // epilogue: +b2, cosine for edges (2g) [rows 0,1] and (2g+1) [rows 2,3]
        float dA = 0.f, nA0 = 0.f, nA1 = 0.f, dB = 0.f, nB0 = 0.f, nB1 = 0.f;
        #pragma unroll
        for (int j = 0; j < 8; j++) {
            float bj = b2s[c8 + j];
            float y0 = a0[j] + bj, y1 = a1[j] + bj;
            float y2 = a2[j] + bj, y3 = a3[j] + bj;
            dA += y0 * y1; nA0 += y0 * y0; nA1 += y1 * y1;
            dB += y2 * y3; nB0 += y2 * y2; nB1 += y3 * y3;
        }
        #pragma unroll
        for (int off = 8; off; off >>= 1) {
            dA  += __shfl_xor_sync(0xffffffffu, dA,  off);
            nA0 += __shfl_xor_sync(0xffffffffu, nA0, off);
            nA1 += __shfl_xor_sync(0xffffffffu, nA1, off);
            dB  += __shfl_xor_sync(0xffffffffu, dB,  off);
            nB0 += __shfl_xor_sync(0xffffffffu, nB0, off);
            nB1 += __shfl_xor_sync(0xffffffffu, nB1, off);
        }
        if ((t & 15) == 0) {
            float ca = dA / (fmaxf(sqrtf(nA0), 1e-8f) * fmaxf(sqrtf(nA1), 1e-8f));
            float cb = dB / (fmaxf(sqrtf(nB0), 1e-8f) * fmaxf(sqrtf(nB1), 1e-8f));
            g_ew[e0 + 2 * g]     = 0.5f * (ca + 1.0f);
            g_ew[e0 + 2 * g + 1] = 0.5f * (cb + 1.0f);
        }
    }
}

// ---------------- GCN pieces ----------------
__global__ void deg_accum(const int* __restrict__ col)
{
    int e = blockIdx.x * blockDim.x + threadIdx.x;
    if (e >= N_EDGESC) return;
    atomicAdd(&g_deg[__ldg(&col[e])], g_ew[e]);
}

__global__ void dinv_k()
{
    int n = blockIdx.x * blockDim.x + threadIdx.x;
    if (n >= N_NODESC) return;
    float d = g_deg[n];
    g_dinv[n] = (d > 0.f) ? rsqrtf(fmaxf(d, 1e-12f)) : 0.f;
}

__global__ void __launch_bounds__(256) gemm64(const float* __restrict__ Aext, int useH,
                                              const float* __restrict__ W)
{
    __shared__ float Ws[64 * 64];
    __shared__ float As[16][65];
    const float* A = useH ? g_h : Aext;
    int t = threadIdx.x;
    for (int i = t; i < 4096; i += 256) Ws[i] = W[i];
    int r0 = blockIdx.x * 16;
    for (int i = t; i < 1024; i += 256)
        As[i >> 6][i & 63] = A[(r0 + (i >> 6)) * 64 + (i & 63)];
    __syncthreads();
    int r = t >> 4, cg = (t & 15) * 4;
    float a0 = 0.f, a1 = 0.f, a2 = 0.f, a3 = 0.f;
    #pragma unroll
    for (int k = 0; k < 64; k++) {
        float av = As[r][k];
        float4 w = *(const float4*)&Ws[k * 64 + cg];
        a0 = fmaf(av, w.x, a0); a1 = fmaf(av, w.y, a1);
        a2 = fmaf(av, w.z, a2); a3 = fmaf(av, w.w, a3);
    }
    float4 o = make_float4(a0, a1, a2, a3);
    *(float4*)&g_xw[(r0 + r) * 64 + cg] = o;
}

__global__ void init_agg()
{
    int t = blockIdx.x * blockDim.x + threadIdx.x;   // N*64 elements
    int n = t >> 6;
    float d = g_dinv[n];
    g_agg[t] = d * d * g_xw[t];
}

__global__ void aggregate(const int* __restrict__ row, const int* __restrict__ col)
{
    unsigned t = blockIdx.x * 256u + threadIdx.x;
    unsigned e = t >> 4;
    if (e >= N_EDGESC) return;
    int l = (t & 15) * 4;
    int r = __ldg(&row[e]), cc = __ldg(&col[e]);
    float w = g_dinv[r] * g_ew[e] * g_dinv[cc];
    float4 v = *(const float4*)&g_xw[r * 64 + l];
    float* dst = &g_agg[cc * 64 + l];
    atomicAdd(dst + 0, w * v.x);
    atomicAdd(dst + 1, w * v.y);
    atomicAdd(dst + 2, w * v.z);
    atomicAdd(dst + 3, w * v.w);
}

__global__ void finish_layer(const float* __restrict__ b)
{
    int t = blockIdx.x * blockDim.x + threadIdx.x;   // N*64
    g_h[t] = fmaxf(g_agg[t] + b[t & 63], 0.f);
}

// ---------------- head: lin1+relu+dropout+lin2 ----------------
__global__ void __launch_bounds__(128) head(
    const float* __restrict__ w1, const float* __restrict__ b1,
    const float* __restrict__ w2, const float* __restrict__ b2,
    float* __restrict__ out, uint32_t kh0, uint32_t kh1)
{
    __shared__ float w1s[64 * 32];
    __shared__ float w2s[32 * 10];
    __shared__ float b1s[32];
    __shared__ float b2s[10];
    int t = threadIdx.x;
    for (int i = t; i < 2048; i += 128) w1s[i] = w1[i];
    for (int i = t; i < 320; i += 128) w2s[i] = w2[i];   // FIX: was `if (t<320)` with 128 threads
    if (t < 32)  b1s[t] = b1[t];
    if (t < 10)  b2s[t] = b2[t];
    __syncthreads();

    int warp = t >> 5, lane = t & 31;
    int rowI = blockIdx.x * 4 + warp;    // N divisible by 4
    const float* hr = &g_h[rowI * 64];
    float acc = b1s[lane];
    #pragma unroll
    for (int k = 0; k < 64; k++)
        acc = fmaf(__ldg(&hr[k]), w1s[k * 32 + lane], acc);
    acc = fmaxf(acc, 0.f);

    // partitionable bits over flat [N,32]
    float u = bits_to_uniform(part_bits(kh0, kh1, (uint32_t)(rowI * 32 + lane)));
    acc = (u < 0.7f) ? acc * INV07 : 0.f;

    #pragma unroll
    for (int c = 0; c < 10; c++) {
        float p = acc * w2s[lane * 10 + c];
        #pragma unroll
        for (int off = 16; off; off >>= 1)
            p += __shfl_xor_sync(0xffffffffu, p, off);
        if (lane == c) out[rowI * 10 + c] = p + b2s[c];
    }
}

// ---------------- launcher ----------------
extern "C" void kernel_launch(void* const* d_in, const int* in_sizes, int n_in,
                              void* d_out, int out_size)
{
    // size-based, order-robust input mapping
    const float *x = 0, *edgenet = 0, *pae_w1 = 0, *pae_w2 = 0;
    const float *lin1_w = 0, *lin1_b = 0, *lin2_w = 0, *lin2_b = 0;
    const int* ei = 0;
    const float* c4096[2] = {0, 0}; int n4096 = 0;
    const float* c64[2]   = {0, 0}; int n64 = 0;
    const float* c128[4]  = {0, 0, 0, 0}; int n128 = 0;
    for (int i = 0; i < n_in; i++) {
        const float* p = (const float*)d_in[i];
        switch (in_sizes[i]) {
            case 6400000: x = p; break;
            case 2000000: ei = (const int*)d_in[i]; break;
            case 4000000: edgenet = p; break;
            case 256:     pae_w1 = p; break;
            case 16384:   pae_w2 = p; break;
            case 4096:    if (n4096 < 2) c4096[n4096++] = p; break;
            case 64:      if (n64 < 2)   c64[n64++] = p; break;
            case 2048:    lin1_w = p; break;
            case 32:      lin1_b = p; break;
            case 320:     lin2_w = p; break;
            case 10:      lin2_b = p; break;
            case 128:     if (n128 < 4)  c128[n128++] = p; break;
        }
    }
    const float* conv1_w = c4096[0];
    const float* conv2_w = c4096[1];
    const float* conv1_b = c64[0];
    const float* conv2_b = c64[1];
    const float* pae_b1   = c128[0];   // first 128-vec in both dict & alpha order
    const float* pae_beta = c128[2];   // third in both orders
    // c128[1] / c128[3]: {gamma, b2} in unknown order -> resolved on device

    float* out = (float*)d_out;
    const int* row = ei;
    const int* col = ei + N_EDGESC;

    // partitionable (foldlike) split: subkey j = full threefry output on counter (0, j)
    uint32_t kp0, kp1, kh0, kh1;
    threefry2x32(0u, 42u, 0u, 0u, kp0, kp1);   // k_pae
    threefry2x32(0u, 42u, 0u, 1u, kh0, kh1);   // k_head

    init_misc<<<(N_NODESC + 255) / 256, 256>>>();
    select_gamma<<<1, 1>>>(c128[1], c128[3]);
    pae_stats<<<512, 128>>>(edgenet, pae_w1, pae_b1);
    pae_finalize<<<1, 256>>>(c128[1], c128[3], pae_beta);
    pae_main<<<888, 128>>>(edgenet, pae_w1, pae_b1, pae_w2, kp0, kp1);

    deg_accum<<<(N_EDGESC + 255) / 256, 256>>>(col);
    dinv_k<<<(N_NODESC + 255) / 256, 256>>>();

    // layer 1
    gemm64<<<N_NODESC / 16, 256>>>(x, 0, conv1_w);
    init_agg<<<N_NODESC * 64 / 256, 256>>>();
    aggregate<<<N_EDGESC * 16 / 256, 256>>>(row, col);
    finish_layer<<<N_NODESC * 64 / 256, 256>>>(conv1_b);

    // layer 2
    gemm64<<<N_NODESC / 16, 256>>>(nullptr, 1, conv2_w);
    init_agg<<<N_NODESC * 64 / 256, 256>>>();
    aggregate<<<N_EDGESC * 16 / 256, 256>>>(row, col);
    finish_layer<<<N_NODESC * 64 / 256, 256>>>(conv2_b);

    head<<<N_NODESC / 4, 128>>>(lin1_w, lin1_b, lin2_w, lin2_b, out, kh0, kh1);
}

// round 10
// speedup vs baseline: 1.0473x; 1.0473x over previous
#include <cuda_runtime.h>
#include <cstdint>

#define N_NODESC 100000
#define N_EDGESC 1000000
#define INV07 (1.0f/0.7f)
#define PAE_S1_OFF 128000000u   // flat offset of s=1 plane in [2,E,128]

// ---------------- scratch (static device globals; no allocation) ----------------
__device__ double g_sums[512];            // [0..255] sum (s*128+c), [256..511] sumsq
__device__ float  g_scale[256];
__device__ float  g_shift[256];
__device__ float  g_b2v[128];
__device__ int    g_sel;                  // 1 if cand1 is gamma, else 3
__device__ float  g_ew[N_EDGESC];
__device__ float  g_deg[N_NODESC];
__device__ float  g_dinv[N_NODESC];
__device__ float  g_xw[N_NODESC * 64];
__device__ float  g_agg[N_NODESC * 64];
__device__ float  g_h[N_NODESC * 64];

// ---------------- JAX threefry2x32 (exact core) ----------------
__host__ __device__ __forceinline__ void threefry2x32(
    uint32_t k0, uint32_t k1, uint32_t x0, uint32_t x1,
    uint32_t& o0, uint32_t& o1)
{
    uint32_t k2 = k0 ^ k1 ^ 0x1BD11BDAu;
    x0 += k0; x1 += k1;
#define TFR(r) { x0 += x1; x1 = (x1 << (r)) | (x1 >> (32 - (r))); x1 ^= x0; }
    TFR(13) TFR(15) TFR(26) TFR(6)   x0 += k1; x1 += k2 + 1u;
    TFR(17) TFR(29) TFR(16) TFR(24)  x0 += k2; x1 += k0 + 2u;
    TFR(13) TFR(15) TFR(26) TFR(6)   x0 += k0; x1 += k1 + 3u;
    TFR(17) TFR(29) TFR(16) TFR(24)  x0 += k1; x1 += k2 + 4u;
    TFR(13) TFR(15) TFR(26) TFR(6)   x0 += k2; x1 += k0 + 5u;
#undef TFR
    o0 = x0; o1 = x1;
}

// partitionable random_bits(32): bits(i) = o0 ^ o1 of threefry(key, hi(i)=0, lo(i)=i)
__device__ __forceinline__ uint32_t part_bits(uint32_t k0, uint32_t k1, uint32_t i)
{
    uint32_t a, b;
    threefry2x32(k0, k1, 0u, i, a, b);
    return a ^ b;
}

__device__ __forceinline__ float bits_to_uniform(uint32_t bits)
{
    return __uint_as_float((bits >> 9) | 0x3f800000u) - 1.0f;
}

// ---------------- init ----------------
__global__ void init_misc()
{
    int t = blockIdx.x * blockDim.x + threadIdx.x;
    if (t < 512) g_sums[t] = 0.0;
    if (t < N_NODESC) g_deg[t] = 1.0f;   // self-loop weight
}

// runtime disambiguation of gamma vs b2 among the two swappable 128-vectors
__global__ void select_gamma(const float* __restrict__ c1, const float* __restrict__ c3)
{
    float s1 = 0.f, s3 = 0.f;
    for (int i = 0; i < 128; i++) { s1 += fabsf(c1[i]); s3 += fabsf(c3[i]); }
    g_sel = (s1 >= s3) ? 1 : 3;
}

// ---------------- PAE BN statistics ----------------
__global__ void __launch_bounds__(128) pae_stats(
    const float* __restrict__ edgenet, const float* __restrict__ w1,
    const float* __restrict__ b1)
{
    int c = threadIdx.x;
    float w10 = w1[c], w11 = w1[128 + c], b1c = b1[c];
    int chunk = (N_EDGESC + gridDim.x - 1) / gridDim.x;
    int e0 = blockIdx.x * chunk;
    int e1 = min(N_EDGESC, e0 + chunk);
    float s0 = 0.f, q0 = 0.f, s1 = 0.f, q1 = 0.f;
    for (int e = e0; e < e1; e++) {
        float4 v = __ldg((const float4*)&edgenet[e * 4]);
        float h0 = fmaxf(fmaf(v.x, w10, fmaf(v.y, w11, b1c)), 0.f);
        float h1 = fmaxf(fmaf(v.z, w10, fmaf(v.w, w11, b1c)), 0.f);
        s0 += h0; q0 += h0 * h0;
        s1 += h1; q1 += h1 * h1;
    }
    atomicAdd(&g_sums[c],       (double)s0);
    atomicAdd(&g_sums[128 + c], (double)s1);
    atomicAdd(&g_sums[256 + c], (double)q0);
    atomicAdd(&g_sums[384 + c], (double)q1);
}

__global__ void pae_finalize(const float* __restrict__ c1, const float* __restrict__ c3,
                             const float* __restrict__ beta)
{
    int i = threadIdx.x;          // 0..255 (s*128+c)
    int c = i & 127;
    const float* gamma = (g_sel == 1) ? c1 : c3;
    const float* b2    = (g_sel == 1) ? c3 : c1;
    if (i < 128) g_b2v[i] = b2[i];
    double mean = g_sums[i] / (double)N_EDGESC;
    double var  = g_sums[256 + i] / (double)N_EDGESC - mean * mean;
    double sc   = (double)gamma[c] / sqrt(var + 1e-5);
    g_scale[i] = (float)sc;
    g_shift[i] = (float)((double)beta[c] - mean * sc);
}

// ---------------- PAE main: BN+dropout+Linear2+cosine per edge ----------------
// persistent blocks; tile = 16 edges (32 rows of 128), GEMM vs w2 (128x128)
// w2 staged ONCE per block into dynamic smem (removes ~32GB of L2 streaming)
__global__ void __launch_bounds__(128) pae_main(
    const float* __restrict__ edgenet, const float* __restrict__ w1,
    const float* __restrict__ b1, const float* __restrict__ w2,
    uint32_t kp0, uint32_t kp1)
{
    extern __shared__ float sm[];
    float* w2s = sm;                    // 128*128 = 16384
    float* hT  = sm + 16384;            // 128 rows(k) x 36 (32 pairs + pad)
    float* edg = hT + 128 * 36;         // 64 floats = 16 edges x 4
    float* b2s = edg + 64;              // 128

    int t = threadIdx.x;
    for (int i = t; i < 16384; i += 128) w2s[i] = w2[i];
    b2s[t] = g_b2v[t];

    int c = t;
    float w10 = w1[c], w11 = w1[128 + c], b1c = b1[c];
    float sc0 = g_scale[c], sh0 = g_shift[c];
    float sc1 = g_scale[128 + c], sh1 = g_shift[128 + c];

    int g  = t >> 4;            // 0..7 -> pair rows 4g..4g+3
    int c8 = (t & 15) * 8;
    int g4 = g * 4;

    const int numTiles = N_EDGESC / 16;
    for (int tile = blockIdx.x; tile < numTiles; tile += gridDim.x) {
        __syncthreads();        // protect hT/edg from previous iteration readers
        if (t < 16)
            *(float4*)&edg[t * 4] = __ldg(&((const float4*)edgenet)[tile * 16 + t]);
        __syncthreads();

        int e0 = tile * 16;
        // phase 1: h (BN + dropout); partitionable bits per element
        #pragma unroll 4
        for (int el = 0; el < 16; el++) {
            float xa0 = edg[el * 4 + 0], xb0 = edg[el * 4 + 1];
            float xa1 = edg[el * 4 + 2], xb1 = edg[el * 4 + 3];
            float hp0 = fmaxf(fmaf(xa0, w10, fmaf(xb0, w11, b1c)), 0.f);
            float hp1 = fmaxf(fmaf(xa1, w10, fmaf(xb1, w11, b1c)), 0.f);
            float hn0 = fmaf(hp0, sc0, sh0);
            float hn1 = fmaf(hp1, sc1, sh1);
            uint32_t i0 = (uint32_t)(e0 + el) * 128u + (uint32_t)c;
            float u0 = bits_to_uniform(part_bits(kp0, kp1, i0));
            float u1 = bits_to_uniform(part_bits(kp0, kp1, i0 + PAE_S1_OFF));
            hT[c * 36 + 2 * el]     = (u0 < 0.7f) ? hn0 * INV07 : 0.f;
            hT[c * 36 + 2 * el + 1] = (u1 < 0.7f) ? hn1 * INV07 : 0.f;
        }
        __syncthreads();

        // phase 2: y[32 rows][128] = h @ w2 ; register tile 4 rows x 8 cols
        float a0[8], a1[8], a2[8], a3[8];
        #pragma unroll
        for (int j = 0; j < 8; j++) { a0[j] = 0.f; a1[j] = 0.f; a2[j] = 0.f; a3[j] = 0.f; }

        #pragma unroll 4
        for (int k = 0; k < 128; k++) {
            float4 wA = *(const float4*)&w2s[k * 128 + c8];
            float4 wB = *(const float4*)&w2s[k * 128 + c8 + 4];
            float4 hv = *(const float4*)&hT[k * 36 + g4];
            float wv[8] = {wA.x, wA.y, wA.z, wA.w, wB.x, wB.y, wB.z, wB.w};
            #pragma unroll
            for (int j = 0; j < 8; j++) {
                a0[j] = fmaf(hv.x, wv[j], a0[j]);
                a1[j] = fmaf(hv.y, wv[j], a1[j]);
                a2[j] = fmaf(hv.z, wv[j], a2[j]);
                a3[j] = fmaf(hv.w, wv[j], a3[j]);
            }
        }

        // epilogue: +b2, cosine for edges (2g) [rows 0,1] and (2g+1) [rows 2,3]
        float dA = 0.f, nA0 = 0.f, nA1 = 0.f, dB = 0.f, nB0 = 0.f, nB1 = 0.f;
        #pragma unroll
        for (int j = 0; j < 8; j++) {
            float bj = b2s[c8 + j];
            float y0 = a0[j] + bj, y1 = a1[j] + bj;
            float y2 = a2[j] + bj, y3 = a3[j] + bj;
            dA += y0 * y1; nA0 += y0 * y0; nA1 += y1 * y1;
            dB += y2 * y3; nB0 += y2 * y2; nB1 += y3 * y3;
        }
        #pragma unroll
        for (int off = 8; off; off >>= 1) {
            dA  += __shfl_xor_sync(0xffffffffu, dA,  off);
            nA0 += __shfl_xor_sync(0xffffffffu, nA0, off);
            nA1 += __shfl_xor_sync(0xffffffffu, nA1, off);
            dB  += __shfl_xor_sync(0xffffffffu, dB,  off);
            nB0 += __shfl_xor_sync(0xffffffffu, nB0, off);
            nB1 += __shfl_xor_sync(0xffffffffu, nB1, off);
        }
        if ((t & 15) == 0) {
            float ca = dA / (fmaxf(sqrtf(nA0), 1e-8f) * fmaxf(sqrtf(nA1), 1e-8f));
            float cb = dB / (fmaxf(sqrtf(nB0), 1e-8f) * fmaxf(sqrtf(nB1), 1e-8f));
            g_ew[e0 + 2 * g]     = 0.5f * (ca + 1.0f);
            g_ew[e0 + 2 * g + 1] = 0.5f * (cb + 1.0f);
        }
    }
}

// ---------------- GCN pieces ----------------
__global__ void deg_accum(const int* __restrict__ col)
{
    int e = blockIdx.x * blockDim.x + threadIdx.x;
    if (e >= N_EDGESC) return;
    atomicAdd(&g_deg[__ldg(&col[e])], g_ew[e]);
}

__global__ void dinv_k()
{
    int n = blockIdx.x * blockDim.x + threadIdx.x;
    if (n >= N_NODESC) return;
    float d = g_deg[n];
    g_dinv[n] = (d > 0.f) ? rsqrtf(fmaxf(d, 1e-12f)) : 0.f;
}

__global__ void __launch_bounds__(256) gemm64(const float* __restrict__ Aext, int useH,
                                              const float* __restrict__ W)
{
    __shared__ float Ws[64 * 64];
    __shared__ float As[16][65];
    const float* A = useH ? g_h : Aext;
    int t = threadIdx.x;
    for (int i = t; i < 4096; i += 256) Ws[i] = W[i];
    int r0 = blockIdx.x * 16;
    for (int i = t; i < 1024; i += 256)
        As[i >> 6][i & 63] = A[(r0 + (i >> 6)) * 64 + (i & 63)];
    __syncthreads();
    int r = t >> 4, cg = (t & 15) * 4;
    float a0 = 0.f, a1 = 0.f, a2 = 0.f, a3 = 0.f;
    #pragma unroll
    for (int k = 0; k < 64; k++) {
        float av = As[r][k];
        float4 w = *(const float4*)&Ws[k * 64 + cg];
        a0 = fmaf(av, w.x, a0); a1 = fmaf(av, w.y, a1);
        a2 = fmaf(av, w.z, a2); a3 = fmaf(av, w.w, a3);
    }
    float4 o = make_float4(a0, a1, a2, a3);
    *(float4*)&g_xw[(r0 + r) * 64 + cg] = o;
}

__global__ void init_agg()
{
    int t = blockIdx.x * blockDim.x + threadIdx.x;   // N*64 elements
    int n = t >> 6;
    float d = g_dinv[n];
    g_agg[t] = d * d * g_xw[t];
}

__global__ void aggregate(const int* __restrict__ row, const int* __restrict__ col)
{
    unsigned t = blockIdx.x * 256u + threadIdx.x;
    unsigned e = t >> 4;
    if (e >= N_EDGESC) return;
    int l = (t & 15) * 4;
    int r = __ldg(&row[e]), cc = __ldg(&col[e]);
    float w = g_dinv[r] * g_ew[e] * g_dinv[cc];
    float4 v = *(const float4*)&g_xw[r * 64 + l];
    float* dst = &g_agg[cc * 64 + l];
    asm volatile("red.global.add.v4.f32 [%0], {%1, %2, %3, %4};"
                 :: "l"(dst), "f"(w * v.x), "f"(w * v.y), "f"(w * v.z), "f"(w * v.w)
                 : "memory");
}

__global__ void finish_layer(const float* __restrict__ b)
{
    int t = blockIdx.x * blockDim.x + threadIdx.x;   // N*64
    g_h[t] = fmaxf(g_agg[t] + b[t & 63], 0.f);
}

// ---------------- head: lin1+relu+dropout+lin2 ----------------
__global__ void __launch_bounds__(128) head(
    const float* __restrict__ w1, const float* __restrict__ b1,
    const float* __restrict__ w2, const float* __restrict__ b2,
    float* __restrict__ out, uint32_t kh0, uint32_t kh1)
{
    __shared__ float w1s[64 * 32];
    __shared__ float w2s[32 * 10];
    __shared__ float b1s[32];
    __shared__ float b2s[10];
    int t = threadIdx.x;
    for (int i = t; i < 2048; i += 128) w1s[i] = w1[i];
    for (int i = t; i < 320; i += 128) w2s[i] = w2[i];
    if (t < 32)  b1s[t] = b1[t];
    if (t < 10)  b2s[t] = b2[t];
    __syncthreads();

    int warp = t >> 5, lane = t & 31;
    int rowI = blockIdx.x * 4 + warp;    // N divisible by 4
    const float* hr = &g_h[rowI * 64];
    float acc = b1s[lane];
    #pragma unroll
    for (int k = 0; k < 64; k++)
        acc = fmaf(__ldg(&hr[k]), w1s[k * 32 + lane], acc);
    acc = fmaxf(acc, 0.f);

    // partitionable bits over flat [N,32]
    float u = bits_to_uniform(part_bits(kh0, kh1, (uint32_t)(rowI * 32 + lane)));
    acc = (u < 0.7f) ? acc * INV07 : 0.f;

    #pragma unroll
    for (int c = 0; c < 10; c++) {
        float p = acc * w2s[lane * 10 + c];
        #pragma unroll
        for (int off = 16; off; off >>= 1)
            p += __shfl_xor_sync(0xffffffffu, p, off);
        if (lane == c) out[rowI * 10 + c] = p + b2s[c];
    }
}

// ---------------- launcher ----------------
extern "C" void kernel_launch(void* const* d_in, const int* in_sizes, int n_in,
                              void* d_out, int out_size)
{
    // size-based, order-robust input mapping
    const float *x = 0, *edgenet = 0, *pae_w1 = 0, *pae_w2 = 0;
    const float *lin1_w = 0, *lin1_b = 0, *lin2_w = 0, *lin2_b = 0;
    const int* ei = 0;
    const float* c4096[2] = {0, 0}; int n4096 = 0;
    const float* c64[2]   = {0, 0}; int n64 = 0;
    const float* c128[4]  = {0, 0, 0, 0}; int n128 = 0;
    for (int i = 0; i < n_in; i++) {
        const float* p = (const float*)d_in[i];
        switch (in_sizes[i]) {
            case 6400000: x = p; break;
            case 2000000: ei = (const int*)d_in[i]; break;
            case 4000000: edgenet = p; break;
            case 256:     pae_w1 = p; break;
            case 16384:   pae_w2 = p; break;
            case 4096:    if (n4096 < 2) c4096[n4096++] = p; break;
            case 64:      if (n64 < 2)   c64[n64++] = p; break;
            case 2048:    lin1_w = p; break;
            case 32:      lin1_b = p; break;
            case 320:     lin2_w = p; break;
            case 10:      lin2_b = p; break;
            case 128:     if (n128 < 4)  c128[n128++] = p; break;
        }
    }
    const float* conv1_w = c4096[0];
    const float* conv2_w = c4096[1];
    const float* conv1_b = c64[0];
    const float* conv2_b = c64[1];
    const float* pae_b1   = c128[0];   // first 128-vec in both dict & alpha order
    const float* pae_beta = c128[2];   // third in both orders
    // c128[1] / c128[3]: {gamma, b2} in unknown order -> resolved on device

    float* out = (float*)d_out;
    const int* row = ei;
    const int* col = ei + N_EDGESC;

    // partitionable (foldlike) split: subkey j = full threefry output on counter (0, j)
    uint32_t kp0, kp1, kh0, kh1;
    threefry2x32(0u, 42u, 0u, 0u, kp0, kp1);   // k_pae
    threefry2x32(0u, 42u, 0u, 1u, kh0, kh1);   // k_head

    const int PAE_SMEM = (16384 + 128 * 36 + 64 + 128) * 4;   // 84736 B
    static int smem_set = 0;
    if (!smem_set) {
        cudaFuncSetAttribute(pae_main, cudaFuncAttributeMaxDynamicSharedMemorySize, PAE_SMEM);
        smem_set = 1;
    }

    init_misc<<<(N_NODESC + 255) / 256, 256>>>();
    select_gamma<<<1, 1>>>(c128[1], c128[3]);
    pae_stats<<<512, 128>>>(edgenet, pae_w1, pae_b1);
    pae_finalize<<<1, 256>>>(c128[1], c128[3], pae_beta);
    pae_main<<<296, 128, PAE_SMEM>>>(edgenet, pae_w1, pae_b1, pae_w2, kp0, kp1);

    deg_accum<<<(N_EDGESC + 255) / 256, 256>>>(col);
    dinv_k<<<(N_NODESC + 255) / 256, 256>>>();

    // layer 1
    gemm64<<<N_NODESC / 16, 256>>>(x, 0, conv1_w);
    init_agg<<<N_NODESC * 64 / 256, 256>>>();
    aggregate<<<N_EDGESC * 16 / 256, 256>>>(row, col);
    finish_layer<<<N_NODESC * 64 / 256, 256>>>(conv1_b);

    // layer 2
    gemm64<<<N_NODESC / 16, 256>>>(nullptr, 1, conv2_w);
    init_agg<<<N_NODESC * 64 / 256, 256>>>();
    aggregate<<<N_EDGESC * 16 / 256, 256>>>(row, col);
    finish_layer<<<N_NODESC * 64 / 256, 256>>>(conv2_b);

    head<<<N_NODESC / 4, 128>>>(lin1_w, lin1_b, lin2_w, lin2_b, out, kh0, kh1);
}